// round 12
// baseline (speedup 1.0000x reference)
#include <cuda_runtime.h>
#include <cuda_bf16.h>
#include <cstdint>

#define D_FEAT    128
#define OUT_DIM   128
#define MAX_NODES 100000
#define MAX_EDGES 600000
#define SCAN_BLK  1024
#define CNT_PAD   102400

#define TM   128          // rows per GEMM tile
#define CK   128          // K per chunk (2 chunks: h then x)
#define LDA  136          // padded bf16 row (272 B stride)
#define GT   256          // GEMM threads (8 warps)

// ---- device scratch (allocation-free) ----
__device__ float g_h[(size_t)MAX_NODES * D_FEAT];
__device__ __align__(16) int g_cnt[CNT_PAD];   // zero-init; self-cleaned each run
__device__ int   g_off[MAX_NODES + 1];
__device__ int   g_cur[MAX_NODES];
__device__ int   g_bsum[128];
__device__ int2  g_edge[MAX_EDGES];
__device__ int   g_bar_cnt;                    // grid barrier state (zero-init)
__device__ int   g_bar_gen;
// bf16 hi/lo images of B chunks: [chunk][part][n=128][k padded to LDA]
__device__ uint4 g_Bimg4[2 * 4352];   // 2 x 69632 B

// ============================ PTX helpers =================================
__device__ __forceinline__ uint32_t smem_u32(const void* p) {
    uint32_t a;
    asm("{ .reg .u64 t; cvta.to.shared.u64 t, %1; cvt.u32.u64 %0, t; }" : "=r"(a) : "l"(p));
    return a;
}
__device__ __forceinline__ void ldsm4(uint32_t* r, uint32_t addr) {
    asm volatile("ldmatrix.sync.aligned.m8n8.x4.shared.b16 {%0,%1,%2,%3}, [%4];"
                 : "=r"(r[0]), "=r"(r[1]), "=r"(r[2]), "=r"(r[3]) : "r"(addr));
}
__device__ __forceinline__ void mma_bf16(float* d, const uint32_t* a,
                                         uint32_t b0, uint32_t b1) {
    asm volatile(
        "mma.sync.aligned.m16n8k16.row.col.f32.bf16.bf16.f32 "
        "{%0,%1,%2,%3}, {%4,%5,%6,%7}, {%8,%9}, {%0,%1,%2,%3};"
        : "+f"(d[0]), "+f"(d[1]), "+f"(d[2]), "+f"(d[3])
        : "r"(a[0]), "r"(a[1]), "r"(a[2]), "r"(a[3]), "r"(b0), "r"(b1));
}
__device__ __forceinline__ uint32_t bf16x2(float y, float x) {
    uint32_t r; asm("cvt.rn.bf16x2.f32 %0, %1, %2;" : "=r"(r) : "f"(y), "f"(x)); return r;
}
__device__ __forceinline__ void cpa16(uint32_t dst, const void* src) {
    asm volatile("cp.async.cg.shared.global [%0], [%1], 16;" :: "r"(dst), "l"(src));
}
__device__ __forceinline__ void cpa16z(uint32_t dst, const void* src, int valid) {
    int sz = valid ? 16 : 0;
    asm volatile("cp.async.cg.shared.global [%0], [%1], 16, %2;"
                 :: "r"(dst), "l"(src), "r"(sz));
}
__device__ __forceinline__ void cpa_commit() {
    asm volatile("cp.async.commit_group;" ::: "memory");
}
template <int N>
__device__ __forceinline__ void cpa_wait() {
    asm volatile("cp.async.wait_group %0;" :: "n"(N) : "memory");
}
// L2-only (skip L1) 16B gather load
__device__ __forceinline__ float4 ldcg4(const float* p) {
    float4 v;
    asm volatile("ld.global.cg.v4.f32 {%0,%1,%2,%3}, [%4];"
                 : "=f"(v.x), "=f"(v.y), "=f"(v.z), "=f"(v.w) : "l"(p));
    return v;
}
// evict-first streaming 16B store
__device__ __forceinline__ void stcs4(float* p, float4 v) {
    asm volatile("st.global.cs.v4.f32 [%0], {%1,%2,%3,%4};"
                 :: "l"(p), "f"(v.x), "f"(v.y), "f"(v.z), "f"(v.w) : "memory");
}

// ---- software grid barrier (all blocks co-resident: nb <= 148) ----
__device__ __forceinline__ void grid_bar(int nb) {
    __syncthreads();
    if (threadIdx.x == 0) {
        __threadfence();
        int gen = *(volatile int*)&g_bar_gen;
        if (atomicAdd(&g_bar_cnt, 1) == nb - 1) {
            g_bar_cnt = 0;
            __threadfence();
            *(volatile int*)&g_bar_gen = gen + 1;
        } else {
            while (*(volatile int*)&g_bar_gen == gen) { }
        }
        __threadfence();
    }
    __syncthreads();
}

// ============ hist + prep fused: edge histogram + B image build ============
__global__ void hist_prep_kernel(const int* __restrict__ rows,
                                 const float* __restrict__ W,
                                 int n, int n_edges) {
    int i = blockIdx.x * blockDim.x + threadIdx.x;
    if (i < 2 * 128 * 128) {
        int c = i >> 14;
        int r = i & 16383;
        int k = r >> 7;
        int nn = r & 127;
        float w = W[(size_t)(c * 128 + k) * OUT_DIM + nn];
        __nv_bfloat16 hb = __float2bfloat16(w);
        __nv_bfloat16 lb = __float2bfloat16(w - __bfloat162float(hb));
        __nv_bfloat16* img = (__nv_bfloat16*)g_Bimg4;
        img[(((size_t)c * 2 + 0) * 128 + nn) * LDA + k] = hb;
        img[(((size_t)c * 2 + 1) * 128 + nn) * LDA + k] = lb;
    }
    if (i < n_edges) atomicAdd(&g_cnt[rows[i]], 1);
}

// ====== fused scan: per-block totals | grid barrier | base + full scan =====
__global__ __launch_bounds__(SCAN_BLK, 1)
void scan_fused_kernel(int n, int nb, int n_edges) {
    __shared__ int wsum[32];
    __shared__ int sbase;
    const int t    = threadIdx.x;
    const int lane = t & 31;
    const int w    = t >> 5;
    const int i    = blockIdx.x * SCAN_BLK + t;

    int v = (i < n) ? g_cnt[i] : 0;
    int s = v;
#pragma unroll
    for (int d = 1; d < 32; d <<= 1) {
        int q = __shfl_up_sync(~0u, s, d);
        if (lane >= d) s += q;
    }
    if (lane == 31) wsum[w] = s;
    __syncthreads();
    if (w == 0) {
        int q = wsum[lane];
#pragma unroll
        for (int d = 1; d < 32; d <<= 1) {
            int r = __shfl_up_sync(~0u, q, d);
            if (lane >= d) q += r;
        }
        wsum[lane] = q;
    }
    __syncthreads();
    int wbase  = (w > 0) ? wsum[w - 1] : 0;
    int s_incl = wbase + s;
    if (t == SCAN_BLK - 1) g_bsum[blockIdx.x] = s_incl;

    grid_bar(nb);

    if (w == 0) {
        int b = 0;
        for (int j = lane; j < (int)blockIdx.x; j += 32) b += g_bsum[j];
#pragma unroll
        for (int o = 16; o > 0; o >>= 1) b += __shfl_xor_sync(~0u, b, o);
        if (lane == 0) sbase = b;
    }
    __syncthreads();
    if (i < n) {
        int o = sbase + s_incl - v;
        g_off[i] = o;
        g_cur[i] = o;
        g_cnt[i] = 0;          // self-clean for next launch
    }
    if (i == n) g_off[n] = n_edges;
}

// ============ scatter: 1 edge/thread, max grid parallelism =================
__global__ void scatter_kernel(const int* __restrict__ rows,
                               const int* __restrict__ cols,
                               const float* __restrict__ vals,
                               int n_edges) {
    int i = blockIdx.x * blockDim.x + threadIdx.x;
    if (i < n_edges) {
        int r = rows[i];
        int p = atomicAdd(&g_cur[r], 1);
        g_edge[p] = make_int2(cols[i], __float_as_int(vals[i]));
    }
}

// ==== SpMM: warp/row, x4 unrolled, L2-only gathers + streaming h stores ====
__global__ void spmm_csr_kernel(const float* __restrict__ x, int n_nodes) {
    int row  = (blockIdx.x * blockDim.x + threadIdx.x) >> 5;
    int lane = threadIdx.x & 31;
    if (row >= n_nodes) return;

    int e  = g_off[row];
    int e1 = g_off[row + 1];

    const float* xl = x + (size_t)lane * 4;

    float4 aA = make_float4(0.f, 0.f, 0.f, 0.f);
    float4 aB = make_float4(0.f, 0.f, 0.f, 0.f);
    for (; e + 4 <= e1; e += 4) {
        int2 e0 = g_edge[e],     e1v = g_edge[e + 1];
        int2 e2 = g_edge[e + 2], e3v = g_edge[e + 3];
        float4 x0 = ldcg4(xl + (size_t)e0.x  * D_FEAT);
        float4 x1 = ldcg4(xl + (size_t)e1v.x * D_FEAT);
        float4 x2 = ldcg4(xl + (size_t)e2.x  * D_FEAT);
        float4 x3 = ldcg4(xl + (size_t)e3v.x * D_FEAT);
        float v0 = __int_as_float(e0.y),  v1 = __int_as_float(e1v.y);
        float v2 = __int_as_float(e2.y),  v3 = __int_as_float(e3v.y);
        aA.x = fmaf(v0, x0.x, aA.x); aA.y = fmaf(v0, x0.y, aA.y);
        aA.z = fmaf(v0, x0.z, aA.z); aA.w = fmaf(v0, x0.w, aA.w);
        aB.x = fmaf(v1, x1.x, aB.x); aB.y = fmaf(v1, x1.y, aB.y);
        aB.z = fmaf(v1, x1.z, aB.z); aB.w = fmaf(v1, x1.w, aB.w);
        aA.x = fmaf(v2, x2.x, aA.x); aA.y = fmaf(v2, x2.y, aA.y);
        aA.z = fmaf(v2, x2.z, aA.z); aA.w = fmaf(v2, x2.w, aA.w);
        aB.x = fmaf(v3, x3.x, aB.x); aB.y = fmaf(v3, x3.y, aB.y);
        aB.z = fmaf(v3, x3.z, aB.z); aB.w = fmaf(v3, x3.w, aB.w);
    }
    for (; e < e1; e++) {
        int2 ev = g_edge[e];
        float4 xv = ldcg4(xl + (size_t)ev.x * D_FEAT);
        float v = __int_as_float(ev.y);
        aA.x = fmaf(v, xv.x, aA.x); aA.y = fmaf(v, xv.y, aA.y);
        aA.z = fmaf(v, xv.z, aA.z); aA.w = fmaf(v, xv.w, aA.w);
    }
    float4 acc = make_float4(aA.x + aB.x, aA.y + aB.y, aA.z + aB.z, aA.w + aB.w);
    stcs4(g_h + (size_t)row * D_FEAT + lane * 4, acc);   // evict-first
}

// ====== GEMM: out = relu([h|x] @ W), cp.async pipelined, 8 warps ==========
// smem: A hi (34816) | A lo (34816) | B hi+lo (69632) | x fp32 scratch (65536)
#define SM_A     0
#define SM_PART  34816
#define SM_B     69632
#define SM_X     139264
#define SM_TOTAL 204800

__global__ __launch_bounds__(GT, 1)
void gemm_mma_kernel(const float* __restrict__ x,
                     float* __restrict__ out,
                     int n_nodes) {
    extern __shared__ char smem[];
    const uint32_t sbase = smem_u32(smem);
    const int tid  = threadIdx.x;
    const int wid  = tid >> 5;
    const int lane = tid & 31;
    const int wm   = wid >> 1;       // 0..3  (32-row strip)
    const int wn   = wid & 1;        // 0..1  (64-col strip)
    const int row0 = blockIdx.x * TM;

    uint32_t pA[2], pB[4];
#pragma unroll
    for (int mf = 0; mf < 2; mf++)
        pA[mf] = sbase + SM_A
               + (uint32_t)((wm * 32 + mf * 16 + (lane & 15)) * (LDA * 2))
               + (uint32_t)((lane >> 4) << 4);
#pragma unroll
    for (int p = 0; p < 4; p++)
        pB[p] = sbase + SM_B
              + (uint32_t)((wn * 64 + p * 16 + (lane & 7) + ((lane >> 4) << 3)) * (LDA * 2))
              + (uint32_t)((lane & 8) << 1);

    float acc[2][8][4];
#pragma unroll
    for (int mf = 0; mf < 2; mf++)
#pragma unroll
        for (int nf = 0; nf < 8; nf++)
#pragma unroll
            for (int q = 0; q < 4; q++) acc[mf][nf][q] = 0.f;

    // ---- group 0: B chunk-0 image via cp.async ----
    {
        const uint4* sB = g_Bimg4;
#pragma unroll
        for (int j = tid; j < 4352; j += GT)
            cpa16(sbase + SM_B + j * 16, sB + j);
    }
    cpa_commit();
    // ---- group 1: x rows (chunk 1) fp32 -> scratch via cp.async ----
    {
#pragma unroll
        for (int j = 0; j < 4096 / GT; j++) {
            int i  = tid + j * GT;
            int r  = i >> 5;
            int kq = i & 31;
            int gr = row0 + r;
            cpa16z(sbase + SM_X + (uint32_t)(r * 512 + kq * 16),
                   x + (size_t)gr * D_FEAT + kq * 4, gr < n_nodes);
        }
    }
    cpa_commit();

    // ---- stage A chunk 0 from g_h (L2 load, split bf16 hi/lo) ----
#pragma unroll
    for (int j = 0; j < (TM * CK / 4) / GT; j++) {
        int i  = tid + j * GT;
        int r  = i >> 5;
        int kq = i & 31;
        int gr = row0 + r;
        float4 v = make_float4(0.f, 0.f, 0.f, 0.f);
        if (gr < n_nodes) v = ldcg4(g_h + (size_t)gr * D_FEAT + kq * 4);
        uint32_t h01 = bf16x2(v.y, v.x);
        uint32_t h23 = bf16x2(v.w, v.z);
        float fx = __uint_as_float(h01 << 16);
        float fy = __uint_as_float(h01 & 0xffff0000u);
        float fz = __uint_as_float(h23 << 16);
        float fw = __uint_as_float(h23 & 0xffff0000u);
        uint32_t l01 = bf16x2(v.y - fy, v.x - fx);
        uint32_t l23 = bf16x2(v.w - fw, v.z - fz);
        char* dst = smem + SM_A + r * (LDA * 2) + kq * 8;
        *(uint2*)dst             = make_uint2(h01, h23);
        *(uint2*)(dst + SM_PART) = make_uint2(l01, l23);
    }
    cpa_wait<1>();
    __syncthreads();

    for (int c = 0; c < 2; c++) {
#pragma unroll
        for (int ks = 0; ks < CK / 16; ks++) {
            const uint32_t k0b = (uint32_t)(ks << 5);
            uint32_t Ah[2][4], Al[2][4];
#pragma unroll
            for (int mf = 0; mf < 2; mf++) {
                ldsm4(Ah[mf], pA[mf] + k0b);
                ldsm4(Al[mf], pA[mf] + SM_PART + k0b);
            }
            uint32_t Bh[4][4], Bl[4][4];
#pragma unroll
            for (int p = 0; p < 4; p++) {
                ldsm4(Bh[p], pB[p] + k0b);
                ldsm4(Bl[p], pB[p] + SM_PART + k0b);
            }
#pragma unroll
            for (int mf = 0; mf < 2; mf++)
#pragma unroll
                for (int p = 0; p < 4; p++) {
                    mma_bf16(acc[mf][2 * p],     Ah[mf], Bh[p][0], Bh[p][1]);
                    mma_bf16(acc[mf][2 * p + 1], Ah[mf], Bh[p][2], Bh[p][3]);
                    mma_bf16(acc[mf][2 * p],     Al[mf], Bh[p][0], Bh[p][1]);
                    mma_bf16(acc[mf][2 * p + 1], Al[mf], Bh[p][2], Bh[p][3]);
                    mma_bf16(acc[mf][2 * p],     Ah[mf], Bl[p][0], Bl[p][1]);
                    mma_bf16(acc[mf][2 * p + 1], Ah[mf], Bl[p][2], Bl[p][3]);
                }
        }

        if (c == 0) {
            cpa_wait<0>();
            __syncthreads();

            {
                const uint4* sB = g_Bimg4 + 4352;
#pragma unroll
                for (int j = tid; j < 4352; j += GT)
                    cpa16(sbase + SM_B + j * 16, sB + j);
            }
            cpa_commit();

#pragma unroll
            for (int j = 0; j < (TM * CK / 4) / GT; j++) {
                int i  = tid + j * GT;
                int r  = i >> 5;
                int kq = i & 31;
                float4 v = *(const float4*)(smem + SM_X + r * 512 + kq * 16);
                uint32_t h01 = bf16x2(v.y, v.x);
                uint32_t h23 = bf16x2(v.w, v.z);
                float fx = __uint_as_float(h01 << 16);
                float fy = __uint_as_float(h01 & 0xffff0000u);
                float fz = __uint_as_float(h23 << 16);
                float fw = __uint_as_float(h23 & 0xffff0000u);
                uint32_t l01 = bf16x2(v.y - fy, v.x - fx);
                uint32_t l23 = bf16x2(v.w - fw, v.z - fz);
                char* dst = smem + SM_A + r * (LDA * 2) + kq * 8;
                *(uint2*)dst             = make_uint2(h01, h23);
                *(uint2*)(dst + SM_PART) = make_uint2(l01, l23);
            }
            cpa_wait<0>();
            __syncthreads();
        }
    }

    // ---- epilogue: relu + store ----
#pragma unroll
    for (int mf = 0; mf < 2; mf++) {
        int gr0 = row0 + wm * 32 + mf * 16 + (lane >> 2);
#pragma unroll
        for (int nf = 0; nf < 8; nf++) {
            int col = wn * 64 + (nf >> 1) * 16 + (nf & 1) * 8 + (lane & 3) * 2;
            float* a = acc[mf][nf];
            if (gr0 < n_nodes) {
                float2 o0 = make_float2(fmaxf(a[0], 0.f), fmaxf(a[1], 0.f));
                *(float2*)(out + (size_t)gr0 * OUT_DIM + col) = o0;
            }
            if (gr0 + 8 < n_nodes) {
                float2 o1 = make_float2(fmaxf(a[2], 0.f), fmaxf(a[3], 0.f));
                *(float2*)(out + (size_t)(gr0 + 8) * OUT_DIM + col) = o1;
            }
        }
    }
}

// ============================== launch =====================================
extern "C" void kernel_launch(void* const* d_in, const int* in_sizes, int n_in,
                              void* d_out, int out_size) {
    const float* x    = (const float*)d_in[0];
    const int*   rows = (const int*)  d_in[1];
    const int*   cols = (const int*)  d_in[2];
    const float* vals = (const float*)d_in[3];
    const float* W    = (const float*)d_in[4];
    float*       out  = (float*)d_out;

    const int n_nodes = in_sizes[0] / D_FEAT;
    const int n_edges = in_sizes[1];
    const int nb      = (n_nodes + SCAN_BLK - 1) / SCAN_BLK;   // 98 <= 148

    hist_prep_kernel<<<(n_edges + 255) / 256, 256>>>(rows, W, n_nodes, n_edges);
    scan_fused_kernel<<<nb, SCAN_BLK>>>(n_nodes, nb, n_edges);
    scatter_kernel<<<(n_edges + 255) / 256, 256>>>(rows, cols, vals, n_edges);

    long long spmm_threads = (long long)n_nodes * 32;
    spmm_csr_kernel<<<(int)((spmm_threads + 255) / 256), 256>>>(x, n_nodes);

    cudaFuncSetAttribute(gemm_mma_kernel,
                         cudaFuncAttributeMaxDynamicSharedMemorySize, SM_TOTAL);
    gemm_mma_kernel<<<(n_nodes + TM - 1) / TM, GT, SM_TOTAL>>>(x, out, n_nodes);
}

// round 13
// speedup vs baseline: 1.0759x; 1.0759x over previous
#include <cuda_runtime.h>
#include <cuda_bf16.h>
#include <cstdint>

#define D_FEAT    128
#define OUT_DIM   128
#define MAX_NODES 100000
#define MAX_EDGES 600000
#define SCAN_BLK  1024
#define CNT_PAD   102400

#define TM   64           // rows per GEMM tile (2 CTAs/SM)
#define CK   128          // K per chunk (2 chunks: h then x)
#define LDA  136          // padded bf16 row (272 B stride)
#define GT   256          // GEMM threads (8 warps)

// ---- device scratch (allocation-free) ----
__device__ float g_h[(size_t)MAX_NODES * D_FEAT];
__device__ __align__(16) int g_cnt[CNT_PAD];   // zero-init; self-cleaned each run
__device__ int   g_off[MAX_NODES + 1];
__device__ int   g_cur[MAX_NODES];
__device__ int   g_bsum[128];
__device__ int2  g_edge[MAX_EDGES];
__device__ int   g_bar_cnt;                    // grid barrier state (zero-init)
__device__ int   g_bar_gen;
// bf16 hi/lo images of B chunks: [chunk][part][n=128][k padded to LDA]
__device__ uint4 g_Bimg4[2 * 4352];   // 2 x 69632 B

// ============================ PTX helpers =================================
__device__ __forceinline__ uint32_t smem_u32(const void* p) {
    uint32_t a;
    asm("{ .reg .u64 t; cvta.to.shared.u64 t, %1; cvt.u32.u64 %0, t; }" : "=r"(a) : "l"(p));
    return a;
}
__device__ __forceinline__ void ldsm4(uint32_t* r, uint32_t addr) {
    asm volatile("ldmatrix.sync.aligned.m8n8.x4.shared.b16 {%0,%1,%2,%3}, [%4];"
                 : "=r"(r[0]), "=r"(r[1]), "=r"(r[2]), "=r"(r[3]) : "r"(addr));
}
__device__ __forceinline__ void mma_bf16(float* d, const uint32_t* a,
                                         uint32_t b0, uint32_t b1) {
    asm volatile(
        "mma.sync.aligned.m16n8k16.row.col.f32.bf16.bf16.f32 "
        "{%0,%1,%2,%3}, {%4,%5,%6,%7}, {%8,%9}, {%0,%1,%2,%3};"
        : "+f"(d[0]), "+f"(d[1]), "+f"(d[2]), "+f"(d[3])
        : "r"(a[0]), "r"(a[1]), "r"(a[2]), "r"(a[3]), "r"(b0), "r"(b1));
}
__device__ __forceinline__ uint32_t bf16x2(float y, float x) {
    uint32_t r; asm("cvt.rn.bf16x2.f32 %0, %1, %2;" : "=r"(r) : "f"(y), "f"(x)); return r;
}
__device__ __forceinline__ void cpa16(uint32_t dst, const void* src) {
    asm volatile("cp.async.cg.shared.global [%0], [%1], 16;" :: "r"(dst), "l"(src));
}
__device__ __forceinline__ void cpa_commit() {
    asm volatile("cp.async.commit_group;" ::: "memory");
}
template <int N>
__device__ __forceinline__ void cpa_wait() {
    asm volatile("cp.async.wait_group %0;" :: "n"(N) : "memory");
}

// ---- software grid barrier (all blocks co-resident: nb <= 148) ----
__device__ __forceinline__ void grid_bar(int nb) {
    __syncthreads();
    if (threadIdx.x == 0) {
        __threadfence();
        int gen = *(volatile int*)&g_bar_gen;
        if (atomicAdd(&g_bar_cnt, 1) == nb - 1) {
            g_bar_cnt = 0;
            __threadfence();
            *(volatile int*)&g_bar_gen = gen + 1;
        } else {
            while (*(volatile int*)&g_bar_gen == gen) { }
        }
        __threadfence();
    }
    __syncthreads();
}

// ============ hist + prep fused: edge histogram + B image build ============
__global__ void hist_prep_kernel(const int* __restrict__ rows,
                                 const float* __restrict__ W,
                                 int n, int n_edges) {
    int i = blockIdx.x * blockDim.x + threadIdx.x;
    if (i < 2 * 128 * 128) {
        int c = i >> 14;
        int r = i & 16383;
        int k = r >> 7;
        int nn = r & 127;
        float w = W[(size_t)(c * 128 + k) * OUT_DIM + nn];
        __nv_bfloat16 hb = __float2bfloat16(w);
        __nv_bfloat16 lb = __float2bfloat16(w - __bfloat162float(hb));
        __nv_bfloat16* img = (__nv_bfloat16*)g_Bimg4;
        img[(((size_t)c * 2 + 0) * 128 + nn) * LDA + k] = hb;
        img[(((size_t)c * 2 + 1) * 128 + nn) * LDA + k] = lb;
    }
    if (i < n_edges) atomicAdd(&g_cnt[rows[i]], 1);
}

// ====== fused scan: per-block totals | grid barrier | base + full scan =====
__global__ __launch_bounds__(SCAN_BLK, 1)
void scan_fused_kernel(int n, int nb, int n_edges) {
    __shared__ int wsum[32];
    __shared__ int sbase;
    const int t    = threadIdx.x;
    const int lane = t & 31;
    const int w    = t >> 5;
    const int i    = blockIdx.x * SCAN_BLK + t;

    int v = (i < n) ? g_cnt[i] : 0;
    int s = v;
#pragma unroll
    for (int d = 1; d < 32; d <<= 1) {
        int q = __shfl_up_sync(~0u, s, d);
        if (lane >= d) s += q;
    }
    if (lane == 31) wsum[w] = s;
    __syncthreads();
    if (w == 0) {
        int q = wsum[lane];
#pragma unroll
        for (int d = 1; d < 32; d <<= 1) {
            int r = __shfl_up_sync(~0u, q, d);
            if (lane >= d) q += r;
        }
        wsum[lane] = q;
    }
    __syncthreads();
    int wbase  = (w > 0) ? wsum[w - 1] : 0;
    int s_incl = wbase + s;
    if (t == SCAN_BLK - 1) g_bsum[blockIdx.x] = s_incl;

    grid_bar(nb);

    if (w == 0) {
        int b = 0;
        for (int j = lane; j < (int)blockIdx.x; j += 32) b += g_bsum[j];
#pragma unroll
        for (int o = 16; o > 0; o >>= 1) b += __shfl_xor_sync(~0u, b, o);
        if (lane == 0) sbase = b;
    }
    __syncthreads();
    if (i < n) {
        int o = sbase + s_incl - v;
        g_off[i] = o;
        g_cur[i] = o;
        g_cnt[i] = 0;          // self-clean for next launch
    }
    if (i == n) g_off[n] = n_edges;
}

// ============ scatter: 1 edge/thread, max grid parallelism =================
__global__ void scatter_kernel(const int* __restrict__ rows,
                               const int* __restrict__ cols,
                               const float* __restrict__ vals,
                               int n_edges) {
    int i = blockIdx.x * blockDim.x + threadIdx.x;
    if (i < n_edges) {
        int r = rows[i];
        int p = atomicAdd(&g_cur[r], 1);
        g_edge[p] = make_int2(cols[i], __float_as_int(vals[i]));
    }
}

// ====== SpMM: 2 rows per warp, 4 gathers in flight, plain loads ============
__global__ void spmm_csr_kernel(const float* __restrict__ x, int n_nodes) {
    int w    = (blockIdx.x * blockDim.x + threadIdx.x) >> 5;
    int lane = threadIdx.x & 31;
    int r0   = w * 2;
    if (r0 >= n_nodes) return;
    int r1   = r0 + 1;
    bool has1 = (r1 < n_nodes);

    int a  = g_off[r0];
    int ae = g_off[r0 + 1];
    int b  = has1 ? ae : 0;
    int be = has1 ? g_off[r1 + 1] : 0;

    float4 A0 = make_float4(0.f, 0.f, 0.f, 0.f);
    float4 A1 = make_float4(0.f, 0.f, 0.f, 0.f);
    float4 B0 = make_float4(0.f, 0.f, 0.f, 0.f);
    float4 B1 = make_float4(0.f, 0.f, 0.f, 0.f);

    // paired loop: 2 edges from EACH row per iteration -> 4 gathers in flight
    while (a + 2 <= ae && b + 2 <= be) {
        int2 ea0 = g_edge[a], ea1 = g_edge[a + 1];
        int2 eb0 = g_edge[b], eb1 = g_edge[b + 1];
        float4 xa0 = ((const float4*)(x + (size_t)ea0.x * D_FEAT))[lane];
        float4 xa1 = ((const float4*)(x + (size_t)ea1.x * D_FEAT))[lane];
        float4 xb0 = ((const float4*)(x + (size_t)eb0.x * D_FEAT))[lane];
        float4 xb1 = ((const float4*)(x + (size_t)eb1.x * D_FEAT))[lane];
        float va0 = __int_as_float(ea0.y), va1 = __int_as_float(ea1.y);
        float vb0 = __int_as_float(eb0.y), vb1 = __int_as_float(eb1.y);
        A0.x = fmaf(va0, xa0.x, A0.x); A0.y = fmaf(va0, xa0.y, A0.y);
        A0.z = fmaf(va0, xa0.z, A0.z); A0.w = fmaf(va0, xa0.w, A0.w);
        A1.x = fmaf(va1, xa1.x, A1.x); A1.y = fmaf(va1, xa1.y, A1.y);
        A1.z = fmaf(va1, xa1.z, A1.z); A1.w = fmaf(va1, xa1.w, A1.w);
        B0.x = fmaf(vb0, xb0.x, B0.x); B0.y = fmaf(vb0, xb0.y, B0.y);
        B0.z = fmaf(vb0, xb0.z, B0.z); B0.w = fmaf(vb0, xb0.w, B0.w);
        B1.x = fmaf(vb1, xb1.x, B1.x); B1.y = fmaf(vb1, xb1.y, B1.y);
        B1.z = fmaf(vb1, xb1.z, B1.z); B1.w = fmaf(vb1, xb1.w, B1.w);
        a += 2; b += 2;
    }
    // drain row 0 (x2)
    for (; a + 2 <= ae; a += 2) {
        int2 e0 = g_edge[a], e1 = g_edge[a + 1];
        float4 x0 = ((const float4*)(x + (size_t)e0.x * D_FEAT))[lane];
        float4 x1 = ((const float4*)(x + (size_t)e1.x * D_FEAT))[lane];
        float v0 = __int_as_float(e0.y), v1 = __int_as_float(e1.y);
        A0.x = fmaf(v0, x0.x, A0.x); A0.y = fmaf(v0, x0.y, A0.y);
        A0.z = fmaf(v0, x0.z, A0.z); A0.w = fmaf(v0, x0.w, A0.w);
        A1.x = fmaf(v1, x1.x, A1.x); A1.y = fmaf(v1, x1.y, A1.y);
        A1.z = fmaf(v1, x1.z, A1.z); A1.w = fmaf(v1, x1.w, A1.w);
    }
    if (a < ae) {
        int2 ev = g_edge[a];
        float4 xv = ((const float4*)(x + (size_t)ev.x * D_FEAT))[lane];
        float v = __int_as_float(ev.y);
        A0.x = fmaf(v, xv.x, A0.x); A0.y = fmaf(v, xv.y, A0.y);
        A0.z = fmaf(v, xv.z, A0.z); A0.w = fmaf(v, xv.w, A0.w);
    }
    // drain row 1 (x2)
    for (; b + 2 <= be; b += 2) {
        int2 e0 = g_edge[b], e1 = g_edge[b + 1];
        float4 x0 = ((const float4*)(x + (size_t)e0.x * D_FEAT))[lane];
        float4 x1 = ((const float4*)(x + (size_t)e1.x * D_FEAT))[lane];
        float v0 = __int_as_float(e0.y), v1 = __int_as_float(e1.y);
        B0.x = fmaf(v0, x0.x, B0.x); B0.y = fmaf(v0, x0.y, B0.y);
        B0.z = fmaf(v0, x0.z, B0.z); B0.w = fmaf(v0, x0.w, B0.w);
        B1.x = fmaf(v1, x1.x, B1.x); B1.y = fmaf(v1, x1.y, B1.y);
        B1.z = fmaf(v1, x1.z, B1.z); B1.w = fmaf(v1, x1.w, B1.w);
    }
    if (b < be) {
        int2 ev = g_edge[b];
        float4 xv = ((const float4*)(x + (size_t)ev.x * D_FEAT))[lane];
        float v = __int_as_float(ev.y);
        B0.x = fmaf(v, xv.x, B0.x); B0.y = fmaf(v, xv.y, B0.y);
        B0.z = fmaf(v, xv.z, B0.z); B0.w = fmaf(v, xv.w, B0.w);
    }

    float4 h0 = make_float4(A0.x + A1.x, A0.y + A1.y, A0.z + A1.z, A0.w + A1.w);
    ((float4*)(g_h + (size_t)r0 * D_FEAT))[lane] = h0;
    if (has1) {
        float4 h1 = make_float4(B0.x + B1.x, B0.y + B1.y, B0.z + B1.z, B0.w + B1.w);
        ((float4*)(g_h + (size_t)r1 * D_FEAT))[lane] = h1;
    }
}

// ====== GEMM: out = relu([h|x] @ W), TM=64, 2 CTAs/SM, per-chunk B =========
// smem: A hi [64][LDA] (17408) | A lo (17408) | B hi (34816) | B lo (34816)
#define SM_A     0
#define SM_PART_A 17408
#define SM_B     34816
#define SM_PART_B 34816
#define SM_TOTAL 104448

__global__ __launch_bounds__(GT, 2)
void gemm_mma_kernel(const float* __restrict__ x,
                     float* __restrict__ out,
                     int n_nodes) {
    extern __shared__ char smem[];
    const uint32_t sbase = smem_u32(smem);
    const int tid  = threadIdx.x;
    const int wid  = tid >> 5;
    const int lane = tid & 31;
    const int wm   = wid >> 2;      // 0..1  (32-row strip)
    const int wn   = wid & 3;       // 0..3  (32-col strip)
    const int row0 = blockIdx.x * TM;

    uint32_t pA[2], pB[2];
#pragma unroll
    for (int mf = 0; mf < 2; mf++)
        pA[mf] = sbase + SM_A
               + (uint32_t)((wm * 32 + mf * 16 + (lane & 15)) * (LDA * 2))
               + (uint32_t)((lane >> 4) << 4);
#pragma unroll
    for (int p = 0; p < 2; p++)
        pB[p] = sbase + SM_B
              + (uint32_t)((wn * 32 + p * 16 + (lane & 7) + ((lane >> 4) << 3)) * (LDA * 2))
              + (uint32_t)((lane & 8) << 1);

    float acc[2][4][4];
#pragma unroll
    for (int mf = 0; mf < 2; mf++)
#pragma unroll
        for (int nf = 0; nf < 4; nf++)
#pragma unroll
            for (int q = 0; q < 4; q++) acc[mf][nf][q] = 0.f;

    for (int c = 0; c < 2; c++) {
        // ---- B chunk image via cp.async (overlaps with A staging below) ----
        {
            const uint4* sB = g_Bimg4 + (size_t)c * 4352;
#pragma unroll
            for (int j = tid; j < 4352; j += GT)
                cpa16(sbase + SM_B + j * 16, sB + j);
        }
        cpa_commit();

        // ---- stage A chunk (h for c=0, x for c=1), split fp32 -> bf16 hi/lo
        const float* src = (c == 0) ? g_h : x;
#pragma unroll
        for (int j = 0; j < (TM * CK / 4) / GT; j++) {       // 8 iters
            int i  = tid + j * GT;
            int r  = i >> 5;
            int kq = i & 31;
            int gr = row0 + r;
            float4 v = make_float4(0.f, 0.f, 0.f, 0.f);
            if (gr < n_nodes) v = ((const float4*)(src + (size_t)gr * D_FEAT))[kq];
            uint32_t h01 = bf16x2(v.y, v.x);
            uint32_t h23 = bf16x2(v.w, v.z);
            float fx = __uint_as_float(h01 << 16);
            float fy = __uint_as_float(h01 & 0xffff0000u);
            float fz = __uint_as_float(h23 << 16);
            float fw = __uint_as_float(h23 & 0xffff0000u);
            uint32_t l01 = bf16x2(v.y - fy, v.x - fx);
            uint32_t l23 = bf16x2(v.w - fw, v.z - fz);
            char* dst = smem + SM_A + r * (LDA * 2) + kq * 8;
            *(uint2*)dst               = make_uint2(h01, h23);
            *(uint2*)(dst + SM_PART_A) = make_uint2(l01, l23);
        }
        cpa_wait<0>();
        __syncthreads();

        // ---- MMA mainloop: 8 k-steps of 16 ----
#pragma unroll
        for (int ks = 0; ks < CK / 16; ks++) {
            const uint32_t k0b = (uint32_t)(ks << 5);
            uint32_t Ah[2][4], Al[2][4];
#pragma unroll
            for (int mf = 0; mf < 2; mf++) {
                ldsm4(Ah[mf], pA[mf] + k0b);
                ldsm4(Al[mf], pA[mf] + SM_PART_A + k0b);
            }
#pragma unroll
            for (int p = 0; p < 2; p++) {
                uint32_t Bh[4], Bl[4];
                ldsm4(Bh, pB[p] + k0b);
                ldsm4(Bl, pB[p] + SM_PART_B + k0b);
#pragma unroll
                for (int mf = 0; mf < 2; mf++) {
                    float* a0 = acc[mf][2 * p];
                    float* a1 = acc[mf][2 * p + 1];
                    mma_bf16(a0, Ah[mf], Bh[0], Bh[1]);
                    mma_bf16(a1, Ah[mf], Bh[2], Bh[3]);
                    mma_bf16(a0, Al[mf], Bh[0], Bh[1]);
                    mma_bf16(a1, Al[mf], Bh[2], Bh[3]);
                    mma_bf16(a0, Ah[mf], Bl[0], Bl[1]);
                    mma_bf16(a1, Ah[mf], Bl[2], Bl[3]);
                }
            }
        }
        if (c == 0) __syncthreads();   // before restaging smem for chunk 1
    }

    // ---- epilogue: relu + store ----
#pragma unroll
    for (int mf = 0; mf < 2; mf++) {
        int r0 = row0 + wm * 32 + mf * 16 + (lane >> 2);
        int r1 = r0 + 8;
#pragma unroll
        for (int nf = 0; nf < 4; nf++) {
            int col = wn * 32 + nf * 8 + (lane & 3) * 2;
            float* a = acc[mf][nf];
            if (r0 < n_nodes) {
                float2 o = make_float2(fmaxf(a[0], 0.f), fmaxf(a[1], 0.f));
                *(float2*)(out + (size_t)r0 * OUT_DIM + col) = o;
            }
            if (r1 < n_nodes) {
                float2 o = make_float2(fmaxf(a[2], 0.f), fmaxf(a[3], 0.f));
                *(float2*)(out + (size_t)r1 * OUT_DIM + col) = o;
            }
        }
    }
}

// ============================== launch =====================================
extern "C" void kernel_launch(void* const* d_in, const int* in_sizes, int n_in,
                              void* d_out, int out_size) {
    const float* x    = (const float*)d_in[0];
    const int*   rows = (const int*)  d_in[1];
    const int*   cols = (const int*)  d_in[2];
    const float* vals = (const float*)d_in[3];
    const float* W    = (const float*)d_in[4];
    float*       out  = (float*)d_out;

    const int n_nodes = in_sizes[0] / D_FEAT;
    const int n_edges = in_sizes[1];
    const int nb      = (n_nodes + SCAN_BLK - 1) / SCAN_BLK;   // 98 <= 148

    hist_prep_kernel<<<(n_edges + 255) / 256, 256>>>(rows, W, n_nodes, n_edges);
    scan_fused_kernel<<<nb, SCAN_BLK>>>(n_nodes, nb, n_edges);
    scatter_kernel<<<(n_edges + 255) / 256, 256>>>(rows, cols, vals, n_edges);

    // SpMM: 2 rows per warp
    int n_warps = (n_nodes + 1) / 2;
    long long spmm_threads = (long long)n_warps * 32;
    spmm_csr_kernel<<<(int)((spmm_threads + 255) / 256), 256>>>(x, n_nodes);

    cudaFuncSetAttribute(gemm_mma_kernel,
                         cudaFuncAttributeMaxDynamicSharedMemorySize, SM_TOTAL);
    gemm_mma_kernel<<<(n_nodes + TM - 1) / TM, GT, SM_TOTAL>>>(x, out, n_nodes);
}

// round 14
// speedup vs baseline: 1.1149x; 1.0363x over previous
#include <cuda_runtime.h>
#include <cuda_bf16.h>
#include <cstdint>

#define D_FEAT    128
#define OUT_DIM   128
#define MAX_NODES 100000
#define MAX_EDGES 600000
#define SCAN_BLK  1024
#define CNT_PAD   102400

#define TM   64           // rows per GEMM tile (2 CTAs/SM)
#define CK   128          // K per chunk (2 chunks: h then x)
#define LDA  136          // padded bf16 row (272 B stride)
#define GT   256          // GEMM threads (8 warps)

// ---- device scratch (allocation-free) ----
// h stored as bf16 hi/lo images: per node 64 uint2 (32 hi, 32 lo) = 512 B
__device__ uint2 g_himg[(size_t)MAX_NODES * 64];
__device__ __align__(16) int g_cnt[CNT_PAD];   // zero-init; self-cleaned each run
__device__ int   g_off[MAX_NODES + 1];
__device__ int   g_cur[MAX_NODES];
__device__ int   g_bsum[128];
__device__ int2  g_edge[MAX_EDGES];
__device__ int   g_bar_cnt;                    // grid barrier state (zero-init)
__device__ int   g_bar_gen;
// bf16 hi/lo images of B chunks: [chunk][part][n=128][k padded to LDA]
__device__ uint4 g_Bimg4[2 * 4352];   // 2 x 69632 B

// ============================ PTX helpers =================================
__device__ __forceinline__ uint32_t smem_u32(const void* p) {
    uint32_t a;
    asm("{ .reg .u64 t; cvta.to.shared.u64 t, %1; cvt.u32.u64 %0, t; }" : "=r"(a) : "l"(p));
    return a;
}
__device__ __forceinline__ void ldsm4(uint32_t* r, uint32_t addr) {
    asm volatile("ldmatrix.sync.aligned.m8n8.x4.shared.b16 {%0,%1,%2,%3}, [%4];"
                 : "=r"(r[0]), "=r"(r[1]), "=r"(r[2]), "=r"(r[3]) : "r"(addr));
}
__device__ __forceinline__ void mma_bf16(float* d, const uint32_t* a,
                                         uint32_t b0, uint32_t b1) {
    asm volatile(
        "mma.sync.aligned.m16n8k16.row.col.f32.bf16.bf16.f32 "
        "{%0,%1,%2,%3}, {%4,%5,%6,%7}, {%8,%9}, {%0,%1,%2,%3};"
        : "+f"(d[0]), "+f"(d[1]), "+f"(d[2]), "+f"(d[3])
        : "r"(a[0]), "r"(a[1]), "r"(a[2]), "r"(a[3]), "r"(b0), "r"(b1));
}
__device__ __forceinline__ uint32_t bf16x2(float y, float x) {
    uint32_t r; asm("cvt.rn.bf16x2.f32 %0, %1, %2;" : "=r"(r) : "f"(y), "f"(x)); return r;
}
__device__ __forceinline__ void cpa16(uint32_t dst, const void* src) {
    asm volatile("cp.async.cg.shared.global [%0], [%1], 16;" :: "r"(dst), "l"(src));
}
__device__ __forceinline__ void cpa16z(uint32_t dst, const void* src, int valid) {
    int sz = valid ? 16 : 0;
    asm volatile("cp.async.cg.shared.global [%0], [%1], 16, %2;"
                 :: "r"(dst), "l"(src), "r"(sz));
}
__device__ __forceinline__ void cpa_commit() {
    asm volatile("cp.async.commit_group;" ::: "memory");
}
template <int N>
__device__ __forceinline__ void cpa_wait() {
    asm volatile("cp.async.wait_group %0;" :: "n"(N) : "memory");
}

// ---- software grid barrier (all blocks co-resident: nb <= 148) ----
__device__ __forceinline__ void grid_bar(int nb) {
    __syncthreads();
    if (threadIdx.x == 0) {
        __threadfence();
        int gen = *(volatile int*)&g_bar_gen;
        if (atomicAdd(&g_bar_cnt, 1) == nb - 1) {
            g_bar_cnt = 0;
            __threadfence();
            *(volatile int*)&g_bar_gen = gen + 1;
        } else {
            while (*(volatile int*)&g_bar_gen == gen) { }
        }
        __threadfence();
    }
    __syncthreads();
}

// ============ hist + prep fused: edge histogram + B image build ============
__global__ void hist_prep_kernel(const int* __restrict__ rows,
                                 const float* __restrict__ W,
                                 int n, int n_edges) {
    int i = blockIdx.x * blockDim.x + threadIdx.x;
    if (i < 2 * 128 * 128) {
        int c = i >> 14;
        int r = i & 16383;
        int k = r >> 7;
        int nn = r & 127;
        float w = W[(size_t)(c * 128 + k) * OUT_DIM + nn];
        __nv_bfloat16 hb = __float2bfloat16(w);
        __nv_bfloat16 lb = __float2bfloat16(w - __bfloat162float(hb));
        __nv_bfloat16* img = (__nv_bfloat16*)g_Bimg4;
        img[(((size_t)c * 2 + 0) * 128 + nn) * LDA + k] = hb;
        img[(((size_t)c * 2 + 1) * 128 + nn) * LDA + k] = lb;
    }
    if (i < n_edges) atomicAdd(&g_cnt[rows[i]], 1);
}

// ====== fused scan: per-block totals | grid barrier | base + full scan =====
__global__ __launch_bounds__(SCAN_BLK, 1)
void scan_fused_kernel(int n, int nb, int n_edges) {
    __shared__ int wsum[32];
    __shared__ int sbase;
    const int t    = threadIdx.x;
    const int lane = t & 31;
    const int w    = t >> 5;
    const int i    = blockIdx.x * SCAN_BLK + t;

    int v = (i < n) ? g_cnt[i] : 0;
    int s = v;
#pragma unroll
    for (int d = 1; d < 32; d <<= 1) {
        int q = __shfl_up_sync(~0u, s, d);
        if (lane >= d) s += q;
    }
    if (lane == 31) wsum[w] = s;
    __syncthreads();
    if (w == 0) {
        int q = wsum[lane];
#pragma unroll
        for (int d = 1; d < 32; d <<= 1) {
            int r = __shfl_up_sync(~0u, q, d);
            if (lane >= d) q += r;
        }
        wsum[lane] = q;
    }
    __syncthreads();
    int wbase  = (w > 0) ? wsum[w - 1] : 0;
    int s_incl = wbase + s;
    if (t == SCAN_BLK - 1) g_bsum[blockIdx.x] = s_incl;

    grid_bar(nb);

    if (w == 0) {
        int b = 0;
        for (int j = lane; j < (int)blockIdx.x; j += 32) b += g_bsum[j];
#pragma unroll
        for (int o = 16; o > 0; o >>= 1) b += __shfl_xor_sync(~0u, b, o);
        if (lane == 0) sbase = b;
    }
    __syncthreads();
    if (i < n) {
        int o = sbase + s_incl - v;
        g_off[i] = o;
        g_cur[i] = o;
        g_cnt[i] = 0;          // self-clean for next launch
    }
    if (i == n) g_off[n] = n_edges;
}

// ============ scatter: 1 edge/thread, max grid parallelism =================
__global__ void scatter_kernel(const int* __restrict__ rows,
                               const int* __restrict__ cols,
                               const float* __restrict__ vals,
                               int n_edges) {
    int i = blockIdx.x * blockDim.x + threadIdx.x;
    if (i < n_edges) {
        int r = rows[i];
        int p = atomicAdd(&g_cur[r], 1);
        g_edge[p] = make_int2(cols[i], __float_as_int(vals[i]));
    }
}

// ====== SpMM: 1 row/warp, batch-8 predicated gathers (MLP=8) ==============
// Emits h directly as bf16 hi/lo image (512 B per node).
__global__ void spmm_csr_kernel(const float* __restrict__ x, int n_nodes) {
    int row  = (blockIdx.x * blockDim.x + threadIdx.x) >> 5;
    int lane = threadIdx.x & 31;
    if (row >= n_nodes) return;

    int e0 = g_off[row];
    int e1 = g_off[row + 1];

    float4 a0 = make_float4(0.f, 0.f, 0.f, 0.f);
    float4 a1 = make_float4(0.f, 0.f, 0.f, 0.f);

    for (int e = e0; e < e1; e += 8) {
        int m = e1 - e;                      // edges left in this batch
        int2 ev[8];
#pragma unroll
        for (int j = 0; j < 8; j++) {
            int idx = (e + j < e1) ? (e + j) : (e1 - 1);
            ev[j] = g_edge[idx];
            if (j >= m) ev[j].y = 0;         // zero the value beyond row end
        }
        float4 xs[8];
#pragma unroll
        for (int j = 0; j < 8; j++)
            xs[j] = ((const float4*)(x + (size_t)ev[j].x * D_FEAT))[lane];
#pragma unroll
        for (int j = 0; j < 8; j++) {
            float v = __int_as_float(ev[j].y);
            if (j & 1) {
                a1.x = fmaf(v, xs[j].x, a1.x); a1.y = fmaf(v, xs[j].y, a1.y);
                a1.z = fmaf(v, xs[j].z, a1.z); a1.w = fmaf(v, xs[j].w, a1.w);
            } else {
                a0.x = fmaf(v, xs[j].x, a0.x); a0.y = fmaf(v, xs[j].y, a0.y);
                a0.z = fmaf(v, xs[j].z, a0.z); a0.w = fmaf(v, xs[j].w, a0.w);
            }
        }
    }

    float4 h = make_float4(a0.x + a1.x, a0.y + a1.y, a0.z + a1.z, a0.w + a1.w);
    // split fp32 -> bf16 hi/lo (identical arithmetic to the old GEMM stage)
    uint32_t h01 = bf16x2(h.y, h.x);
    uint32_t h23 = bf16x2(h.w, h.z);
    float fx = __uint_as_float(h01 << 16);
    float fy = __uint_as_float(h01 & 0xffff0000u);
    float fz = __uint_as_float(h23 << 16);
    float fw = __uint_as_float(h23 & 0xffff0000u);
    uint32_t l01 = bf16x2(h.y - fy, h.x - fx);
    uint32_t l23 = bf16x2(h.w - fw, h.z - fz);
    g_himg[(size_t)row * 64 + lane]      = make_uint2(h01, h23);   // hi
    g_himg[(size_t)row * 64 + 32 + lane] = make_uint2(l01, l23);   // lo
}

// ====== GEMM: out = relu([h|x] @ W), TM=64, 2 CTAs/SM ======================
// chunk 0: A image streamed straight from g_himg via cp.async (no convert)
// chunk 1: A staged from x with fp32->bf16 hi/lo split
// smem: A hi [64][LDA] (17408) | A lo (17408) | B hi (34816) | B lo (34816)
#define SM_A      0
#define SM_PART_A 17408
#define SM_B      34816
#define SM_PART_B 34816
#define SM_TOTAL  104448

__global__ __launch_bounds__(GT, 2)
void gemm_mma_kernel(const float* __restrict__ x,
                     float* __restrict__ out,
                     int n_nodes) {
    extern __shared__ char smem[];
    const uint32_t sbase = smem_u32(smem);
    const int tid  = threadIdx.x;
    const int wid  = tid >> 5;
    const int lane = tid & 31;
    const int wm   = wid >> 2;      // 0..1  (32-row strip)
    const int wn   = wid & 3;       // 0..3  (32-col strip)
    const int row0 = blockIdx.x * TM;

    uint32_t pA[2], pB[2];
#pragma unroll
    for (int mf = 0; mf < 2; mf++)
        pA[mf] = sbase + SM_A
               + (uint32_t)((wm * 32 + mf * 16 + (lane & 15)) * (LDA * 2))
               + (uint32_t)((lane >> 4) << 4);
#pragma unroll
    for (int p = 0; p < 2; p++)
        pB[p] = sbase + SM_B
              + (uint32_t)((wn * 32 + p * 16 + (lane & 7) + ((lane >> 4) << 3)) * (LDA * 2))
              + (uint32_t)((lane & 8) << 1);

    float acc[2][4][4];
#pragma unroll
    for (int mf = 0; mf < 2; mf++)
#pragma unroll
        for (int nf = 0; nf < 4; nf++)
#pragma unroll
            for (int q = 0; q < 4; q++) acc[mf][nf][q] = 0.f;

    for (int c = 0; c < 2; c++) {
        // ---- B chunk image via cp.async ----
        {
            const uint4* sB = g_Bimg4 + (size_t)c * 4352;
#pragma unroll
            for (int j = tid; j < 4352; j += GT)
                cpa16(sbase + SM_B + j * 16, sB + j);
        }

        if (c == 0) {
            // ---- A chunk 0: stream h bf16 image directly (2048 chunks) ----
#pragma unroll
            for (int j = 0; j < 2048 / GT; j++) {       // 8 per thread
                int i    = tid + j * GT;
                int r    = i >> 5;           // tile row
                int part = (i >> 4) & 1;     // 0 = hi, 1 = lo
                int kq   = i & 15;           // 16B chunk within 256B
                int gr   = row0 + r;
                uint32_t dst = sbase + SM_A + part * SM_PART_A
                             + (uint32_t)(r * (LDA * 2) + kq * 16);
                const char* src = (const char*)(g_himg + (size_t)gr * 64 + part * 32)
                                + kq * 16;
                cpa16z(dst, src, gr < n_nodes);
            }
            cpa_commit();
            cpa_wait<0>();
            __syncthreads();
        } else {
            cpa_commit();
            // ---- A chunk 1: stage from x (fp32 -> bf16 hi/lo) ----
#pragma unroll
            for (int j = 0; j < (TM * CK / 4) / GT; j++) {   // 8 iters
                int i  = tid + j * GT;
                int r  = i >> 5;
                int kq = i & 31;
                int gr = row0 + r;
                float4 v = make_float4(0.f, 0.f, 0.f, 0.f);
                if (gr < n_nodes) v = ((const float4*)(x + (size_t)gr * D_FEAT))[kq];
                uint32_t h01 = bf16x2(v.y, v.x);
                uint32_t h23 = bf16x2(v.w, v.z);
                float fx = __uint_as_float(h01 << 16);
                float fy = __uint_as_float(h01 & 0xffff0000u);
                float fz = __uint_as_float(h23 << 16);
                float fw = __uint_as_float(h23 & 0xffff0000u);
                uint32_t l01 = bf16x2(v.y - fy, v.x - fx);
                uint32_t l23 = bf16x2(v.w - fw, v.z - fz);
                char* dst = smem + SM_A + r * (LDA * 2) + kq * 8;
                *(uint2*)dst               = make_uint2(h01, h23);
                *(uint2*)(dst + SM_PART_A) = make_uint2(l01, l23);
            }
            cpa_wait<0>();
            __syncthreads();
        }

        // ---- MMA mainloop: 8 k-steps of 16 ----
#pragma unroll
        for (int ks = 0; ks < CK / 16; ks++) {
            const uint32_t k0b = (uint32_t)(ks << 5);
            uint32_t Ah[2][4], Al[2][4];
#pragma unroll
            for (int mf = 0; mf < 2; mf++) {
                ldsm4(Ah[mf], pA[mf] + k0b);
                ldsm4(Al[mf], pA[mf] + SM_PART_A + k0b);
            }
#pragma unroll
            for (int p = 0; p < 2; p++) {
                uint32_t Bh[4], Bl[4];
                ldsm4(Bh, pB[p] + k0b);
                ldsm4(Bl, pB[p] + SM_PART_B + k0b);
#pragma unroll
                for (int mf = 0; mf < 2; mf++) {
                    float* a0 = acc[mf][2 * p];
                    float* a1 = acc[mf][2 * p + 1];
                    mma_bf16(a0, Ah[mf], Bh[0], Bh[1]);
                    mma_bf16(a1, Ah[mf], Bh[2], Bh[3]);
                    mma_bf16(a0, Al[mf], Bh[0], Bh[1]);
                    mma_bf16(a1, Al[mf], Bh[2], Bh[3]);
                    mma_bf16(a0, Ah[mf], Bl[0], Bl[1]);
                    mma_bf16(a1, Ah[mf], Bl[2], Bl[3]);
                }
            }
        }
        if (c == 0) __syncthreads();   // before restaging smem for chunk 1
    }

    // ---- epilogue: relu + store ----
#pragma unroll
    for (int mf = 0; mf < 2; mf++) {
        int r0 = row0 + wm * 32 + mf * 16 + (lane >> 2);
        int r1 = r0 + 8;
#pragma unroll
        for (int nf = 0; nf < 4; nf++) {
            int col = wn * 32 + nf * 8 + (lane & 3) * 2;
            float* a = acc[mf][nf];
            if (r0 < n_nodes) {
                float2 o = make_float2(fmaxf(a[0], 0.f), fmaxf(a[1], 0.f));
                *(float2*)(out + (size_t)r0 * OUT_DIM + col) = o;
            }
            if (r1 < n_nodes) {
                float2 o = make_float2(fmaxf(a[2], 0.f), fmaxf(a[3], 0.f));
                *(float2*)(out + (size_t)r1 * OUT_DIM + col) = o;
            }
        }
    }
}

// ============================== launch =====================================
extern "C" void kernel_launch(void* const* d_in, const int* in_sizes, int n_in,
                              void* d_out, int out_size) {
    const float* x    = (const float*)d_in[0];
    const int*   rows = (const int*)  d_in[1];
    const int*   cols = (const int*)  d_in[2];
    const float* vals = (const float*)d_in[3];
    const float* W    = (const float*)d_in[4];
    float*       out  = (float*)d_out;

    const int n_nodes = in_sizes[0] / D_FEAT;
    const int n_edges = in_sizes[1];
    const int nb      = (n_nodes + SCAN_BLK - 1) / SCAN_BLK;   // 98 <= 148

    hist_prep_kernel<<<(n_edges + 255) / 256, 256>>>(rows, W, n_nodes, n_edges);
    scan_fused_kernel<<<nb, SCAN_BLK>>>(n_nodes, nb, n_edges);
    scatter_kernel<<<(n_edges + 255) / 256, 256>>>(rows, cols, vals, n_edges);

    // SpMM: 1 row per warp, batch-8 gathers
    long long spmm_threads = (long long)n_nodes * 32;
    spmm_csr_kernel<<<(int)((spmm_threads + 255) / 256), 256>>>(x, n_nodes);

    cudaFuncSetAttribute(gemm_mma_kernel,
                         cudaFuncAttributeMaxDynamicSharedMemorySize, SM_TOTAL);
    gemm_mma_kernel<<<(n_nodes + TM - 1) / TM, GT, SM_TOTAL>>>(x, out, n_nodes);
}

// round 15
// speedup vs baseline: 1.1329x; 1.0161x over previous
#include <cuda_runtime.h>
#include <cuda_bf16.h>
#include <cstdint>

#define D_FEAT    128
#define OUT_DIM   128
#define MAX_NODES 100000
#define MAX_EDGES 600000
#define SCAN_BLK  1024
#define CNT_PAD   102400

#define TM   64           // rows per GEMM tile (2 CTAs/SM)
#define CK   128          // K per chunk (2 chunks: h then x)
#define LDA  136          // padded bf16 row (272 B stride)
#define GT   256          // GEMM threads (8 warps)

// ---- device scratch (allocation-free) ----
// h stored as bf16 hi/lo images: per node 64 uint2 (32 hi, 32 lo) = 512 B
__device__ uint2 g_himg[(size_t)MAX_NODES * 64];
__device__ __align__(16) int g_cnt[CNT_PAD];   // zero-init; self-cleaned each run
__device__ int   g_off[MAX_NODES + 1];
__device__ int   g_cur[MAX_NODES];
__device__ int   g_bsum[128];
__device__ int2  g_edge[MAX_EDGES + 8];        // +8 pad (zero-init: col=0 safe)
__device__ int   g_bar_cnt;                    // grid barrier state (zero-init)
__device__ int   g_bar_gen;
// bf16 hi/lo images of B chunks: [chunk][part][n=128][k padded to LDA]
__device__ uint4 g_Bimg4[2 * 4352];   // 2 x 69632 B

// ============================ PTX helpers =================================
__device__ __forceinline__ uint32_t smem_u32(const void* p) {
    uint32_t a;
    asm("{ .reg .u64 t; cvta.to.shared.u64 t, %1; cvt.u32.u64 %0, t; }" : "=r"(a) : "l"(p));
    return a;
}
__device__ __forceinline__ void ldsm4(uint32_t* r, uint32_t addr) {
    asm volatile("ldmatrix.sync.aligned.m8n8.x4.shared.b16 {%0,%1,%2,%3}, [%4];"
                 : "=r"(r[0]), "=r"(r[1]), "=r"(r[2]), "=r"(r[3]) : "r"(addr));
}
__device__ __forceinline__ void mma_bf16(float* d, const uint32_t* a,
                                         uint32_t b0, uint32_t b1) {
    asm volatile(
        "mma.sync.aligned.m16n8k16.row.col.f32.bf16.bf16.f32 "
        "{%0,%1,%2,%3}, {%4,%5,%6,%7}, {%8,%9}, {%0,%1,%2,%3};"
        : "+f"(d[0]), "+f"(d[1]), "+f"(d[2]), "+f"(d[3])
        : "r"(a[0]), "r"(a[1]), "r"(a[2]), "r"(a[3]), "r"(b0), "r"(b1));
}
__device__ __forceinline__ uint32_t bf16x2(float y, float x) {
    uint32_t r; asm("cvt.rn.bf16x2.f32 %0, %1, %2;" : "=r"(r) : "f"(y), "f"(x)); return r;
}
__device__ __forceinline__ void cpa16(uint32_t dst, const void* src) {
    asm volatile("cp.async.cg.shared.global [%0], [%1], 16;" :: "r"(dst), "l"(src));
}
__device__ __forceinline__ void cpa16z(uint32_t dst, const void* src, int valid) {
    int sz = valid ? 16 : 0;
    asm volatile("cp.async.cg.shared.global [%0], [%1], 16, %2;"
                 :: "r"(dst), "l"(src), "r"(sz));
}
__device__ __forceinline__ void cpa_commit() {
    asm volatile("cp.async.commit_group;" ::: "memory");
}
template <int N>
__device__ __forceinline__ void cpa_wait() {
    asm volatile("cp.async.wait_group %0;" :: "n"(N) : "memory");
}

// ---- software grid barrier (all blocks co-resident: nb <= 148) ----
__device__ __forceinline__ void grid_bar(int nb) {
    __syncthreads();
    if (threadIdx.x == 0) {
        __threadfence();
        int gen = *(volatile int*)&g_bar_gen;
        if (atomicAdd(&g_bar_cnt, 1) == nb - 1) {
            g_bar_cnt = 0;
            __threadfence();
            *(volatile int*)&g_bar_gen = gen + 1;
        } else {
            while (*(volatile int*)&g_bar_gen == gen) { }
        }
        __threadfence();
    }
    __syncthreads();
}

// ============ hist + prep fused: edge histogram + B image build ============
__global__ void hist_prep_kernel(const int* __restrict__ rows,
                                 const float* __restrict__ W,
                                 int n, int n_edges) {
    int i = blockIdx.x * blockDim.x + threadIdx.x;
    if (i < 2 * 128 * 128) {
        int c = i >> 14;
        int r = i & 16383;
        int k = r >> 7;
        int nn = r & 127;
        float w = W[(size_t)(c * 128 + k) * OUT_DIM + nn];
        __nv_bfloat16 hb = __float2bfloat16(w);
        __nv_bfloat16 lb = __float2bfloat16(w - __bfloat162float(hb));
        __nv_bfloat16* img = (__nv_bfloat16*)g_Bimg4;
        img[(((size_t)c * 2 + 0) * 128 + nn) * LDA + k] = hb;
        img[(((size_t)c * 2 + 1) * 128 + nn) * LDA + k] = lb;
    }
    if (i < n_edges) atomicAdd(&g_cnt[rows[i]], 1);
}

// ====== fused scan: per-block totals | grid barrier | base + full scan =====
__global__ __launch_bounds__(SCAN_BLK, 1)
void scan_fused_kernel(int n, int nb, int n_edges) {
    __shared__ int wsum[32];
    __shared__ int sbase;
    const int t    = threadIdx.x;
    const int lane = t & 31;
    const int w    = t >> 5;
    const int i    = blockIdx.x * SCAN_BLK + t;

    int v = (i < n) ? g_cnt[i] : 0;
    int s = v;
#pragma unroll
    for (int d = 1; d < 32; d <<= 1) {
        int q = __shfl_up_sync(~0u, s, d);
        if (lane >= d) s += q;
    }
    if (lane == 31) wsum[w] = s;
    __syncthreads();
    if (w == 0) {
        int q = wsum[lane];
#pragma unroll
        for (int d = 1; d < 32; d <<= 1) {
            int r = __shfl_up_sync(~0u, q, d);
            if (lane >= d) q += r;
        }
        wsum[lane] = q;
    }
    __syncthreads();
    int wbase  = (w > 0) ? wsum[w - 1] : 0;
    int s_incl = wbase + s;
    if (t == SCAN_BLK - 1) g_bsum[blockIdx.x] = s_incl;

    grid_bar(nb);

    if (w == 0) {
        int b = 0;
        for (int j = lane; j < (int)blockIdx.x; j += 32) b += g_bsum[j];
#pragma unroll
        for (int o = 16; o > 0; o >>= 1) b += __shfl_xor_sync(~0u, b, o);
        if (lane == 0) sbase = b;
    }
    __syncthreads();
    if (i < n) {
        int o = sbase + s_incl - v;
        g_off[i] = o;
        g_cur[i] = o;
        g_cnt[i] = 0;          // self-clean for next launch
    }
    if (i == n) g_off[n] = n_edges;
}

// ============ scatter: 1 edge/thread, max grid parallelism =================
__global__ void scatter_kernel(const int* __restrict__ rows,
                               const int* __restrict__ cols,
                               const float* __restrict__ vals,
                               int n_edges) {
    int i = blockIdx.x * blockDim.x + threadIdx.x;
    if (i < n_edges) {
        int r = rows[i];
        int p = atomicAdd(&g_cur[r], 1);
        g_edge[p] = make_int2(cols[i], __float_as_int(vals[i]));
    }
}

// ====== SpMM: 1 row/warp, batch-4 unconditional gathers (MLP=4) ===========
// g_edge is padded by 8 zero entries -> unconditional descriptor loads are
// safe (col=0); values beyond the row end are zeroed by a single compare.
// Emits h directly as bf16 hi/lo image (512 B per node).
__global__ void spmm_csr_kernel(const float* __restrict__ x, int n_nodes) {
    int row  = (blockIdx.x * blockDim.x + threadIdx.x) >> 5;
    int lane = threadIdx.x & 31;
    if (row >= n_nodes) return;

    int e0 = g_off[row];
    int e1 = g_off[row + 1];

    float4 a0 = make_float4(0.f, 0.f, 0.f, 0.f);
    float4 a1 = make_float4(0.f, 0.f, 0.f, 0.f);

    for (int e = e0; e < e1; e += 4) {
        int2 ev0 = g_edge[e];
        int2 ev1 = g_edge[e + 1];
        int2 ev2 = g_edge[e + 2];
        int2 ev3 = g_edge[e + 3];
        // zero values beyond row end (descriptors themselves are safe)
        if (e + 1 >= e1) ev1.y = 0;
        if (e + 2 >= e1) ev2.y = 0;
        if (e + 3 >= e1) ev3.y = 0;
        float4 x0 = ((const float4*)(x + (size_t)ev0.x * D_FEAT))[lane];
        float4 x1 = ((const float4*)(x + (size_t)ev1.x * D_FEAT))[lane];
        float4 x2 = ((const float4*)(x + (size_t)ev2.x * D_FEAT))[lane];
        float4 x3 = ((const float4*)(x + (size_t)ev3.x * D_FEAT))[lane];
        float v0 = __int_as_float(ev0.y), v1 = __int_as_float(ev1.y);
        float v2 = __int_as_float(ev2.y), v3 = __int_as_float(ev3.y);
        a0.x = fmaf(v0, x0.x, a0.x); a0.y = fmaf(v0, x0.y, a0.y);
        a0.z = fmaf(v0, x0.z, a0.z); a0.w = fmaf(v0, x0.w, a0.w);
        a1.x = fmaf(v1, x1.x, a1.x); a1.y = fmaf(v1, x1.y, a1.y);
        a1.z = fmaf(v1, x1.z, a1.z); a1.w = fmaf(v1, x1.w, a1.w);
        a0.x = fmaf(v2, x2.x, a0.x); a0.y = fmaf(v2, x2.y, a0.y);
        a0.z = fmaf(v2, x2.z, a0.z); a0.w = fmaf(v2, x2.w, a0.w);
        a1.x = fmaf(v3, x3.x, a1.x); a1.y = fmaf(v3, x3.y, a1.y);
        a1.z = fmaf(v3, x3.z, a1.z); a1.w = fmaf(v3, x3.w, a1.w);
    }

    float4 h = make_float4(a0.x + a1.x, a0.y + a1.y, a0.z + a1.z, a0.w + a1.w);
    // split fp32 -> bf16 hi/lo
    uint32_t h01 = bf16x2(h.y, h.x);
    uint32_t h23 = bf16x2(h.w, h.z);
    float fx = __uint_as_float(h01 << 16);
    float fy = __uint_as_float(h01 & 0xffff0000u);
    float fz = __uint_as_float(h23 << 16);
    float fw = __uint_as_float(h23 & 0xffff0000u);
    uint32_t l01 = bf16x2(h.y - fy, h.x - fx);
    uint32_t l23 = bf16x2(h.w - fw, h.z - fz);
    g_himg[(size_t)row * 64 + lane]      = make_uint2(h01, h23);   // hi
    g_himg[(size_t)row * 64 + 32 + lane] = make_uint2(l01, l23);   // lo
}

// ====== GEMM: out = relu([h|x] @ W), TM=64, 2 CTAs/SM ======================
// chunk 0: A image streamed straight from g_himg via cp.async (no convert)
// chunk 1: A staged from x with fp32->bf16 hi/lo split
// smem: A hi [64][LDA] (17408) | A lo (17408) | B hi (34816) | B lo (34816)
#define SM_A      0
#define SM_PART_A 17408
#define SM_B      34816
#define SM_PART_B 34816
#define SM_TOTAL  104448

__global__ __launch_bounds__(GT, 2)
void gemm_mma_kernel(const float* __restrict__ x,
                     float* __restrict__ out,
                     int n_nodes) {
    extern __shared__ char smem[];
    const uint32_t sbase = smem_u32(smem);
    const int tid  = threadIdx.x;
    const int wid  = tid >> 5;
    const int lane = tid & 31;
    const int wm   = wid >> 2;      // 0..1  (32-row strip)
    const int wn   = wid & 3;       // 0..3  (32-col strip)
    const int row0 = blockIdx.x * TM;

    uint32_t pA[2], pB[2];
#pragma unroll
    for (int mf = 0; mf < 2; mf++)
        pA[mf] = sbase + SM_A
               + (uint32_t)((wm * 32 + mf * 16 + (lane & 15)) * (LDA * 2))
               + (uint32_t)((lane >> 4) << 4);
#pragma unroll
    for (int p = 0; p < 2; p++)
        pB[p] = sbase + SM_B
              + (uint32_t)((wn * 32 + p * 16 + (lane & 7) + ((lane >> 4) << 3)) * (LDA * 2))
              + (uint32_t)((lane & 8) << 1);

    float acc[2][4][4];
#pragma unroll
    for (int mf = 0; mf < 2; mf++)
#pragma unroll
        for (int nf = 0; nf < 4; nf++)
#pragma unroll
            for (int q = 0; q < 4; q++) acc[mf][nf][q] = 0.f;

    for (int c = 0; c < 2; c++) {
        // ---- B chunk image via cp.async ----
        {
            const uint4* sB = g_Bimg4 + (size_t)c * 4352;
#pragma unroll
            for (int j = tid; j < 4352; j += GT)
                cpa16(sbase + SM_B + j * 16, sB + j);
        }

        if (c == 0) {
            // ---- A chunk 0: stream h bf16 image directly (2048 chunks) ----
#pragma unroll
            for (int j = 0; j < 2048 / GT; j++) {       // 8 per thread
                int i    = tid + j * GT;
                int r    = i >> 5;           // tile row
                int part = (i >> 4) & 1;     // 0 = hi, 1 = lo
                int kq   = i & 15;           // 16B chunk within 256B
                int gr   = row0 + r;
                uint32_t dst = sbase + SM_A + part * SM_PART_A
                             + (uint32_t)(r * (LDA * 2) + kq * 16);
                const char* src = (const char*)(g_himg + (size_t)gr * 64 + part * 32)
                                + kq * 16;
                cpa16z(dst, src, gr < n_nodes);
            }
            cpa_commit();
            cpa_wait<0>();
            __syncthreads();
        } else {
            cpa_commit();
            // ---- A chunk 1: stage from x (fp32 -> bf16 hi/lo) ----
#pragma unroll
            for (int j = 0; j < (TM * CK / 4) / GT; j++) {   // 8 iters
                int i  = tid + j * GT;
                int r  = i >> 5;
                int kq = i & 31;
                int gr = row0 + r;
                float4 v = make_float4(0.f, 0.f, 0.f, 0.f);
                if (gr < n_nodes) v = ((const float4*)(x + (size_t)gr * D_FEAT))[kq];
                uint32_t h01 = bf16x2(v.y, v.x);
                uint32_t h23 = bf16x2(v.w, v.z);
                float fx = __uint_as_float(h01 << 16);
                float fy = __uint_as_float(h01 & 0xffff0000u);
                float fz = __uint_as_float(h23 << 16);
                float fw = __uint_as_float(h23 & 0xffff0000u);
                uint32_t l01 = bf16x2(v.y - fy, v.x - fx);
                uint32_t l23 = bf16x2(v.w - fw, v.z - fz);
                char* dst = smem + SM_A + r * (LDA * 2) + kq * 8;
                *(uint2*)dst               = make_uint2(h01, h23);
                *(uint2*)(dst + SM_PART_A) = make_uint2(l01, l23);
            }
            cpa_wait<0>();
            __syncthreads();
        }

        // ---- MMA mainloop: 8 k-steps of 16 ----
#pragma unroll
        for (int ks = 0; ks < CK / 16; ks++) {
            const uint32_t k0b = (uint32_t)(ks << 5);
            uint32_t Ah[2][4], Al[2][4];
#pragma unroll
            for (int mf = 0; mf < 2; mf++) {
                ldsm4(Ah[mf], pA[mf] + k0b);
                ldsm4(Al[mf], pA[mf] + SM_PART_A + k0b);
            }
#pragma unroll
            for (int p = 0; p < 2; p++) {
                uint32_t Bh[4], Bl[4];
                ldsm4(Bh, pB[p] + k0b);
                ldsm4(Bl, pB[p] + SM_PART_B + k0b);
#pragma unroll
                for (int mf = 0; mf < 2; mf++) {
                    float* a0 = acc[mf][2 * p];
                    float* a1 = acc[mf][2 * p + 1];
                    mma_bf16(a0, Ah[mf], Bh[0], Bh[1]);
                    mma_bf16(a1, Ah[mf], Bh[2], Bh[3]);
                    mma_bf16(a0, Al[mf], Bh[0], Bh[1]);
                    mma_bf16(a1, Al[mf], Bh[2], Bh[3]);
                    mma_bf16(a0, Ah[mf], Bl[0], Bl[1]);
                    mma_bf16(a1, Ah[mf], Bl[2], Bl[3]);
                }
            }
        }
        if (c == 0) __syncthreads();   // before restaging smem for chunk 1
    }

    // ---- epilogue: relu + store ----
#pragma unroll
    for (int mf = 0; mf < 2; mf++) {
        int r0 = row0 + wm * 32 + mf * 16 + (lane >> 2);
        int r1 = r0 + 8;
#pragma unroll
        for (int nf = 0; nf < 4; nf++) {
            int col = wn * 32 + nf * 8 + (lane & 3) * 2;
            float* a = acc[mf][nf];
            if (r0 < n_nodes) {
                float2 o = make_float2(fmaxf(a[0], 0.f), fmaxf(a[1], 0.f));
                *(float2*)(out + (size_t)r0 * OUT_DIM + col) = o;
            }
            if (r1 < n_nodes) {
                float2 o = make_float2(fmaxf(a[2], 0.f), fmaxf(a[3], 0.f));
                *(float2*)(out + (size_t)r1 * OUT_DIM + col) = o;
            }
        }
    }
}

// ============================== launch =====================================
extern "C" void kernel_launch(void* const* d_in, const int* in_sizes, int n_in,
                              void* d_out, int out_size) {
    const float* x    = (const float*)d_in[0];
    const int*   rows = (const int*)  d_in[1];
    const int*   cols = (const int*)  d_in[2];
    const float* vals = (const float*)d_in[3];
    const float* W    = (const float*)d_in[4];
    float*       out  = (float*)d_out;

    const int n_nodes = in_sizes[0] / D_FEAT;
    const int n_edges = in_sizes[1];
    const int nb      = (n_nodes + SCAN_BLK - 1) / SCAN_BLK;   // 98 <= 148

    hist_prep_kernel<<<(n_edges + 255) / 256, 256>>>(rows, W, n_nodes, n_edges);
    scan_fused_kernel<<<nb, SCAN_BLK>>>(n_nodes, nb, n_edges);
    scatter_kernel<<<(n_edges + 255) / 256, 256>>>(rows, cols, vals, n_edges);

    // SpMM: 1 row per warp, batch-4 unconditional gathers
    long long spmm_threads = (long long)n_nodes * 32;
    spmm_csr_kernel<<<(int)((spmm_threads + 255) / 256), 256>>>(x, n_nodes);

    cudaFuncSetAttribute(gemm_mma_kernel,
                         cudaFuncAttributeMaxDynamicSharedMemorySize, SM_TOTAL);
    gemm_mma_kernel<<<(n_nodes + TM - 1) / TM, GT, SM_TOTAL>>>(x, out, n_nodes);
}